// round 8
// baseline (speedup 1.0000x reference)
#include <cuda_runtime.h>
#include <cstdint>
#include <math.h>

#define B_  64
#define T_  512
#define N_  128
#define H_  512
#define G_  2048              // 4*H
#define BT_ (B_ * T_)         // 32768
#define NBLK 128

typedef unsigned long long ull;

#define FMA2(d, a, b, c) asm("fma.rn.f32x2 %0, %1, %2, %3;" : "=l"(d) : "l"(a), "l"(b), "l"(c))
#define PACK2(d, lo, hi) asm("mov.b64 %0, {%1, %2};" : "=l"(d) : "f"(lo), "f"(hi))
#define UNPACK2(lo, hi, v) asm("mov.b64 {%0, %1}, %2;" : "=f"(lo), "=f"(hi) : "l"(v))

#define CP_ASYNC16(dst_smem_u32, src_gmem_ptr) \
    asm volatile("cp.async.cg.shared.global [%0], [%1], 16;" :: "r"(dst_smem_u32), "l"(src_gmem_ptr) : "memory")
#define CP_COMMIT() asm volatile("cp.async.commit_group;" ::: "memory")
#define CP_WAIT(n)  asm volatile("cp.async.wait_group %0;" :: "n"(n) : "memory")

// -------- device scratch --------
__device__ float g_xg[(size_t)BT_ * G_];     // X@Wx + b, [bt][4H]
__device__ float g_hs[(size_t)BT_ * H_];     // h history [b][t][H]
__device__ float g_hT2[2][256 * 128];        // h mirror, k-pair interleaved: [kp][b][2]
__device__ float g_lpart[2048];
__device__ volatile int g_flags[128];        // [bg*32 + ug] (reset by xg_gemm)

// ============================================================
// Kernel A: xg = X @ Wx + b  (unchanged; also resets flags)
// ============================================================
__global__ void __launch_bounds__(256) xg_gemm(
    const float* __restrict__ X, const float* __restrict__ Wx,
    const float* __restrict__ bias)
{
    __shared__ float Xst[64 * 68];
    __shared__ float Wsd[64 * 128];
    int tid = threadIdx.x;
    if (blockIdx.x == 0 && blockIdx.y == 0 && tid < 128) g_flags[tid] = 0;

    int m0 = blockIdx.y * 64;
    int n0 = blockIdx.x * 64;
    int cx = tid & 15, ry = tid >> 4;
    int c8 = cx * 8;

    ull acc[2][4] = {};
    for (int kc = 0; kc < 128; kc += 64) {
        __syncthreads();
        #pragma unroll
        for (int i = 0; i < 16; i++) {
            int idx = tid + i * 256;
            int k = idx & 63, r = idx >> 6;
            Xst[k * 68 + r] = X[(size_t)(m0 + r) * 128 + kc + k];
        }
        #pragma unroll
        for (int i = 0; i < 32; i++) {
            int idx = tid + i * 256;
            int k = idx >> 7, rem = idx & 127;
            Wsd[k * 128 + rem] = Wx[(size_t)(kc + k) * G_ + n0 + (rem >> 1)];
        }
        __syncthreads();
        #pragma unroll 8
        for (int k = 0; k < 64; k++) {
            ulonglong2 hq  = *(const ulonglong2*)&Xst[k * 68 + ry * 4];
            ulonglong2 wq0 = *(const ulonglong2*)&Wsd[k * 128 + c8];
            ulonglong2 wq1 = *(const ulonglong2*)&Wsd[k * 128 + c8 + 4];
            FMA2(acc[0][0], hq.x, wq0.x, acc[0][0]);
            FMA2(acc[0][1], hq.x, wq0.y, acc[0][1]);
            FMA2(acc[0][2], hq.x, wq1.x, acc[0][2]);
            FMA2(acc[0][3], hq.x, wq1.y, acc[0][3]);
            FMA2(acc[1][0], hq.y, wq0.x, acc[1][0]);
            FMA2(acc[1][1], hq.y, wq0.y, acc[1][1]);
            FMA2(acc[1][2], hq.y, wq1.x, acc[1][2]);
            FMA2(acc[1][3], hq.y, wq1.y, acc[1][3]);
        }
    }
    float4 bb = *(const float4*)&bias[n0 + cx * 4];
    #pragma unroll
    for (int j = 0; j < 2; j++) {
        float lo[4], hi[4];
        #pragma unroll
        for (int cp = 0; cp < 4; cp++) UNPACK2(lo[cp], hi[cp], acc[j][cp]);
        int row0 = m0 + ry * 4 + j * 2;
        *(float4*)&g_xg[(size_t)row0 * G_ + n0 + cx * 4] =
            make_float4(lo[0] + bb.x, lo[1] + bb.y, lo[2] + bb.z, lo[3] + bb.w);
        *(float4*)&g_xg[(size_t)(row0 + 1) * G_ + n0 + cx * 4] =
            make_float4(hi[0] + bb.x, hi[1] + bb.y, hi[2] + bb.z, hi[3] + bb.w);
    }
}

// ============================================================
// Kernel B: persistent LSTM scan with k-parity f32x2 packing.
// Block (ug, bg): 64 cols x 16 batches, K=512 (256 k-pairs).
// Thread (cg:8, bh:2, kq:16): 8 cols x 8 batches x 16 k-pairs.
//   W2  [256 kp][132] : (w[2kp][c], w[2kp+1][c]) interleaved, 4-float row pad
//   h2  [256 kp][36]  : (h[2kp][b], h[2kp+1][b]) interleaved (in scr region)
//   red [16 kq][1028] : folded partials (scr region, after h reads done)
// Zero packs, zero inner-loop address ALU (immediates after unroll).
// ============================================================
#define W2_FLOATS   (256 * 132)             // 33792
#define SCR_FLOATS  (16 * 1028)             // 16448 (>= h2's 256*36=9216)
#define SMEM_SCAN   ((W2_FLOATS + SCR_FLOATS + 1024 + 256) * 4)   // 206080 B

__global__ void __launch_bounds__(256, 1) lstm_scan(const float* __restrict__ Wh)
{
    extern __shared__ float smem[];
    float* W2     = smem;                        // [256][132]
    float* scr    = smem + W2_FLOATS;            // h2 [256][36] / red [16][1028]
    float* gsum   = scr + SCR_FLOATS;            // [16 b][64 c]
    float* hstage = gsum + 1024;                 // [16 u][16 b]

    int tid = threadIdx.x;
    int bid = blockIdx.x;
    int ug = bid >> 2, bg = bid & 3;
    int u0 = ug * 16;

    // stage W2 once: k-parity interleaved, padded rows
    for (int i = 0; i < 128; i++) {
        int idx = tid + i * 256;                  // 0..32767
        int k = idx >> 6, c = idx & 63;
        W2[(k >> 1) * 132 + c * 2 + (k & 1)] =
            Wh[(size_t)k * G_ + (c >> 4) * 512 + u0 + (c & 15)];
    }

    int cg = tid >> 5, bh = (tid >> 4) & 1, kq = tid & 15;
    int u_l = tid & 15, b_l = tid >> 4;           // phase-2 cell
    int u_cell = u0 + u_l, b_cell = bg * 16 + b_l;
    int rc = tid >> 2, rbq = tid & 3;             // reduce-read coords
    float creg = 0.0f;

    uint32_t scr_base = (uint32_t)__cvta_generic_to_shared(scr);

    __syncthreads();

    for (int t = 0; t < T_; t++) {
        // prefetch xg (hides DRAM latency behind the flag wait)
        float xgv[4];
        {
            size_t xoff = ((size_t)(b_cell * T_ + t)) * G_;
            #pragma unroll
            for (int g = 0; g < 4; g++)
                xgv[g] = g_xg[xoff + g * 512 + u_cell];
        }

        if (t > 0) {
            if (tid < 32) {
                while (g_flags[bg * 32 + tid] < t) { __nanosleep(32); }
                __threadfence();
            }
            __syncthreads();
            const float* src = g_hT2[t & 1];
            // 4 chunks of 64 kp (8KB each); contiguous 128B rows per kp
            #pragma unroll
            for (int chg = 0; chg < 4; chg++) {
                #pragma unroll
                for (int q = 0; q < 2; q++) {
                    int f = tid + q * 256;            // 0..511 16B-chunks
                    int kp = chg * 64 + (f >> 3), j = f & 7;
                    CP_ASYNC16(scr_base + (unsigned)((kp * 36 + j * 4) * 4),
                               (const void*)&src[(size_t)kp * 128 + bg * 32 + j * 4]);
                }
                CP_COMMIT();
            }
        } else {
            #pragma unroll
            for (int i = 0; i < 9; i++)               // zero h2 region (2304 float4)
                *(float4*)&scr[(tid + i * 256) * 4] = make_float4(0.f, 0.f, 0.f, 0.f);
        }

        ull acc[8][8] = {};   // [col ci][batch bi], f32x2 over k-parity

        #pragma unroll
        for (int ch = 0; ch < 4; ch++) {
            if (t > 0) {
                switch (ch) {
                    case 0: CP_WAIT(3); break;
                    case 1: CP_WAIT(2); break;
                    case 2: CP_WAIT(1); break;
                    default: CP_WAIT(0); break;
                }
            }
            __syncthreads();
            #pragma unroll
            for (int ii = 0; ii < 4; ii++) {
                int kp = ch * 64 + ii * 16 + kq;
                const ulonglong2* wr = (const ulonglong2*)&W2[kp * 132 + cg * 16];
                ulonglong2 wa = wr[0], wb = wr[1], wc = wr[2], wd = wr[3];
                const ulonglong2* hr = (const ulonglong2*)&scr[kp * 36 + bh * 16];
                ulonglong2 ha = hr[0], hb = hr[1], hc = hr[2], hd = hr[3];
                ull w[8] = {wa.x, wa.y, wb.x, wb.y, wc.x, wc.y, wd.x, wd.y};
                ull h[8] = {ha.x, ha.y, hb.x, hb.y, hc.x, hc.y, hd.x, hd.y};
                #pragma unroll
                for (int ci = 0; ci < 8; ci++)
                    #pragma unroll
                    for (int bi = 0; bi < 8; bi++)
                        FMA2(acc[ci][bi], w[ci], h[bi], acc[ci][bi]);
            }
        }

        // ---- fold k-parity + 16-way kq reduce through scr ----
        __syncthreads();          // all h2 reads done; scr becomes red
        #pragma unroll
        for (int ci = 0; ci < 8; ci++) {
            float s[8];
            #pragma unroll
            for (int bi = 0; bi < 8; bi++) {
                float lo, hi; UNPACK2(lo, hi, acc[ci][bi]);
                s[bi] = lo + hi;
            }
            int base = kq * 1028 + (cg * 8 + ci) * 16 + bh * 8;
            *(float4*)&scr[base]     = make_float4(s[0], s[1], s[2], s[3]);
            *(float4*)&scr[base + 4] = make_float4(s[4], s[5], s[6], s[7]);
        }
        __syncthreads();

        // read-sum: thread -> col rc, batches rbq*4..+4
        {
            float4 vs = make_float4(0.f, 0.f, 0.f, 0.f);
            #pragma unroll
            for (int kqi = 0; kqi < 16; kqi++) {
                float4 v = *(const float4*)&scr[kqi * 1028 + rc * 16 + rbq * 4];
                vs.x += v.x; vs.y += v.y; vs.z += v.z; vs.w += v.w;
            }
            gsum[(rbq * 4 + 0) * 64 + rc] = vs.x;
            gsum[(rbq * 4 + 1) * 64 + rc] = vs.y;
            gsum[(rbq * 4 + 2) * 64 + rc] = vs.z;
            gsum[(rbq * 4 + 3) * 64 + rc] = vs.w;
        }
        __syncthreads();

        // phase 2: one cell per thread
        {
            float s0 = gsum[b_l * 64 + 0 * 16 + u_l] + xgv[0];   // i
            float s1 = gsum[b_l * 64 + 1 * 16 + u_l] + xgv[1];   // j
            float s2 = gsum[b_l * 64 + 2 * 16 + u_l] + xgv[2];   // f
            float s3 = gsum[b_l * 64 + 3 * 16 + u_l] + xgv[3];   // o
            float ig = 1.0f / (1.0f + expf(-s0));
            float jg = tanhf(s1);
            float fg = 1.0f / (1.0f + expf(-(s2 + 1.0f)));       // forget_bias = 1
            float og = 1.0f / (1.0f + expf(-s3));
            creg = fg * creg + ig * jg;
            float h = og * tanhf(creg);
            hstage[u_l * 16 + b_l] = h;
            g_hs[((size_t)(b_cell * T_ + t)) * H_ + u_cell] = h;
        }
        __syncthreads();
        if (tid < 128) {       // k-pair interleaved mirror write (coalesced ull)
            int kpi = tid >> 4, bi = tid & 15;
            ull hv; PACK2(hv, hstage[(kpi * 2) * 16 + bi], hstage[(kpi * 2 + 1) * 16 + bi]);
            ((ull*)g_hT2[(t + 1) & 1])[(size_t)(ug * 8 + kpi) * 64 + bg * 16 + bi] = hv;
        }
        __threadfence();
        __syncthreads();
        if (tid == 0) g_flags[bg * 32 + ug] = t + 1;
    }
}

// ============================================================
// Kernel C: out_loss (unchanged)
// ============================================================
__global__ void __launch_bounds__(256) out_loss(
    const float* __restrict__ Wd, const float* __restrict__ bd,
    const float* __restrict__ Y)
{
    __shared__ float h_s[512 * 20];
    __shared__ float red[8];
    int tid = threadIdx.x;
    int row0 = blockIdx.x * 16;

    #pragma unroll
    for (int i = 0; i < 32; i++) {
        int idx = tid + i * 256;
        int r = idx >> 9, k = idx & 511;
        h_s[k * 20 + r] = g_hs[(size_t)(row0 + r) * H_ + k];
    }
    __syncthreads();

    int cc = tid & 127;
    int rh = tid >> 7;
    ull acc2[4] = {};
    #pragma unroll 4
    for (int k = 0; k < 512; k++) {
        float w = Wd[(size_t)k * N_ + cc];
        ull wd; PACK2(wd, w, w);
        ulonglong2 ha = *(const ulonglong2*)&h_s[k * 20 + rh * 8];
        ulonglong2 hb = *(const ulonglong2*)&h_s[k * 20 + rh * 8 + 4];
        FMA2(acc2[0], ha.x, wd, acc2[0]);
        FMA2(acc2[1], ha.y, wd, acc2[1]);
        FMA2(acc2[2], hb.x, wd, acc2[2]);
        FMA2(acc2[3], hb.y, wd, acc2[3]);
    }
    float accv[8];
    #pragma unroll
    for (int p = 0; p < 4; p++) UNPACK2(accv[2 * p], accv[2 * p + 1], acc2[p]);

    float bdc = bd[cc];
    float lsum = 0.0f;
    #pragma unroll
    for (int i = 0; i < 8; i++) {
        int row = row0 + rh * 8 + i;
        float logit = 1.0f / (1.0f + expf(-(accv[i] + bdc)));
        float d = Y[(size_t)row * N_ + cc] - logit;
        lsum += d * d;
    }
    #pragma unroll
    for (int o = 16; o; o >>= 1) lsum += __shfl_xor_sync(0xFFFFFFFFu, lsum, o);
    if ((tid & 31) == 0) red[tid >> 5] = lsum;
    __syncthreads();
    if (tid == 0) {
        float ssum = 0.0f;
        #pragma unroll
        for (int i = 0; i < 8; i++) ssum += red[i];
        g_lpart[blockIdx.x] = ssum;
    }
}

// ============================================================
__global__ void finalize(float* __restrict__ out)
{
    __shared__ float red[8];
    int tid = threadIdx.x;
    float sv = 0.0f;
    for (int i = tid; i < 2048; i += 256) sv += g_lpart[i];
    #pragma unroll
    for (int o = 16; o; o >>= 1) sv += __shfl_xor_sync(0xFFFFFFFFu, sv, o);
    if ((tid & 31) == 0) red[tid >> 5] = sv;
    __syncthreads();
    if (tid == 0) {
        float tt = 0.0f;
        #pragma unroll
        for (int i = 0; i < 8; i++) tt += red[i];
        out[0] = tt * (100.0f / ((float)B_ * (float)T_ * (float)N_));
    }
}

// ============================================================
extern "C" void kernel_launch(void* const* d_in, const int* in_sizes, int n_in,
                              void* d_out, int out_size)
{
    const float* X  = (const float*)d_in[0];
    const float* Y  = (const float*)d_in[1];
    const float* Wx = (const float*)d_in[2];
    const float* Wh = (const float*)d_in[3];
    const float* b  = (const float*)d_in[4];
    const float* Wd = (const float*)d_in[5];
    const float* bd = (const float*)d_in[6];
    (void)in_sizes; (void)n_in; (void)out_size;

    cudaFuncSetAttribute(lstm_scan, cudaFuncAttributeMaxDynamicSharedMemorySize, SMEM_SCAN);

    dim3 gA(G_ / 64, BT_ / 64);
    xg_gemm<<<gA, 256>>>(X, Wx, b);             // also resets g_flags
    lstm_scan<<<NBLK, 256, SMEM_SCAN>>>(Wh);
    out_loss<<<BT_ / 16, 256>>>(Wd, bd, Y);
    finalize<<<1, 256>>>((float*)d_out);
}

// round 9
// speedup vs baseline: 1.2350x; 1.2350x over previous
#include <cuda_runtime.h>
#include <cstdint>
#include <math.h>

#define B_  64
#define T_  512
#define N_  128
#define H_  512
#define G_  2048              // 4*H
#define BT_ (B_ * T_)         // 32768
#define NBLK 128

typedef unsigned long long ull;

#define FMA2(d, a, b, c) asm("fma.rn.f32x2 %0, %1, %2, %3;" : "=l"(d) : "l"(a), "l"(b), "l"(c))
#define PACK2(d, lo, hi) asm("mov.b64 %0, {%1, %2};" : "=l"(d) : "f"(lo), "f"(hi))
#define UNPACK2(lo, hi, v) asm("mov.b64 {%0, %1}, %2;" : "=f"(lo), "=f"(hi) : "l"(v))

#define CP_ASYNC16(dst_smem_u32, src_gmem_ptr) \
    asm volatile("cp.async.cg.shared.global [%0], [%1], 16;" :: "r"(dst_smem_u32), "l"(src_gmem_ptr) : "memory")
#define CP_COMMIT() asm volatile("cp.async.commit_group;" ::: "memory")
#define CP_WAIT(n)  asm volatile("cp.async.wait_group %0;" :: "n"(n) : "memory")

// -------- device scratch --------
__device__ float g_xg[(size_t)BT_ * G_];     // X@Wx + b, [bt][4H]
__device__ float g_hs[(size_t)BT_ * H_];     // h history [b][t][H]
__device__ float g_hT2[2][256 * 128];        // h mirror, k-pair interleaved: [kp][b][2]
__device__ float g_lpart[2048];
__device__ int   g_done[128];                // per-bg counters at [bg*32] (128B apart)

__device__ __forceinline__ float sigf(float x) {
    return __fdividef(1.0f, 1.0f + __expf(-x));
}
__device__ __forceinline__ float tanhfast(float x) {
    return __fdividef(2.0f, 1.0f + __expf(-2.0f * x)) - 1.0f;
}

// ============================================================
// Kernel A: xg = X @ Wx + b  (also resets sync counters)
// ============================================================
__global__ void __launch_bounds__(256) xg_gemm(
    const float* __restrict__ X, const float* __restrict__ Wx,
    const float* __restrict__ bias)
{
    __shared__ float Xst[64 * 68];
    __shared__ float Wsd[64 * 128];
    int tid = threadIdx.x;
    if (blockIdx.x == 0 && blockIdx.y == 0 && tid < 128) g_done[tid] = 0;

    int m0 = blockIdx.y * 64;
    int n0 = blockIdx.x * 64;
    int cx = tid & 15, ry = tid >> 4;
    int c8 = cx * 8;

    ull acc[2][4] = {};
    for (int kc = 0; kc < 128; kc += 64) {
        __syncthreads();
        #pragma unroll
        for (int i = 0; i < 16; i++) {
            int idx = tid + i * 256;
            int k = idx & 63, r = idx >> 6;
            Xst[k * 68 + r] = X[(size_t)(m0 + r) * 128 + kc + k];
        }
        #pragma unroll
        for (int i = 0; i < 32; i++) {
            int idx = tid + i * 256;
            int k = idx >> 7, rem = idx & 127;
            Wsd[k * 128 + rem] = Wx[(size_t)(kc + k) * G_ + n0 + (rem >> 1)];
        }
        __syncthreads();
        #pragma unroll 8
        for (int k = 0; k < 64; k++) {
            ulonglong2 hq  = *(const ulonglong2*)&Xst[k * 68 + ry * 4];
            ulonglong2 wq0 = *(const ulonglong2*)&Wsd[k * 128 + c8];
            ulonglong2 wq1 = *(const ulonglong2*)&Wsd[k * 128 + c8 + 4];
            FMA2(acc[0][0], hq.x, wq0.x, acc[0][0]);
            FMA2(acc[0][1], hq.x, wq0.y, acc[0][1]);
            FMA2(acc[0][2], hq.x, wq1.x, acc[0][2]);
            FMA2(acc[0][3], hq.x, wq1.y, acc[0][3]);
            FMA2(acc[1][0], hq.y, wq0.x, acc[1][0]);
            FMA2(acc[1][1], hq.y, wq0.y, acc[1][1]);
            FMA2(acc[1][2], hq.y, wq1.x, acc[1][2]);
            FMA2(acc[1][3], hq.y, wq1.y, acc[1][3]);
        }
    }
    float4 bb = *(const float4*)&bias[n0 + cx * 4];
    #pragma unroll
    for (int j = 0; j < 2; j++) {
        float lo[4], hi[4];
        #pragma unroll
        for (int cp = 0; cp < 4; cp++) UNPACK2(lo[cp], hi[cp], acc[j][cp]);
        int row0 = m0 + ry * 4 + j * 2;
        *(float4*)&g_xg[(size_t)row0 * G_ + n0 + cx * 4] =
            make_float4(lo[0] + bb.x, lo[1] + bb.y, lo[2] + bb.z, lo[3] + bb.w);
        *(float4*)&g_xg[(size_t)(row0 + 1) * G_ + n0 + cx * 4] =
            make_float4(hi[0] + bb.x, hi[1] + bb.y, hi[2] + bb.z, hi[3] + bb.w);
    }
}

// ============================================================
// Kernel B: persistent LSTM scan (k-parity f32x2 core, R8) with
// single-counter release/acquire sync and MUFU phase-2.
// ============================================================
#define W2_FLOATS   (256 * 132)             // 33792
#define SCR_FLOATS  (16 * 1028)             // 16448 (>= h2's 256*36=9216)
#define SMEM_SCAN   ((W2_FLOATS + SCR_FLOATS + 1024 + 256) * 4)   // 206080 B

__global__ void __launch_bounds__(256, 1) lstm_scan(const float* __restrict__ Wh)
{
    extern __shared__ float smem[];
    float* W2     = smem;                        // [256][132]
    float* scr    = smem + W2_FLOATS;            // h2 [256][36] / red [16][1028]
    float* gsum   = scr + SCR_FLOATS;            // [16 b][64 c]
    float* hstage = gsum + 1024;                 // [16 u][16 b]

    int tid = threadIdx.x;
    int bid = blockIdx.x;
    int ug = bid >> 2, bg = bid & 3;
    int u0 = ug * 16;
    int* donep = &g_done[bg * 32];

    // stage W2 once: k-parity interleaved, padded rows
    for (int i = 0; i < 128; i++) {
        int idx = tid + i * 256;                  // 0..32767
        int k = idx >> 6, c = idx & 63;
        W2[(k >> 1) * 132 + c * 2 + (k & 1)] =
            Wh[(size_t)k * G_ + (c >> 4) * 512 + u0 + (c & 15)];
    }

    int cg = tid >> 5, bh = (tid >> 4) & 1, kq = tid & 15;
    int u_l = tid & 15, b_l = tid >> 4;           // phase-2 cell
    int u_cell = u0 + u_l, b_cell = bg * 16 + b_l;
    int rc = tid >> 2, rbq = tid & 3;             // reduce-read coords
    float creg = 0.0f;

    uint32_t scr_base = (uint32_t)__cvta_generic_to_shared(scr);

    __syncthreads();

    for (int t = 0; t < T_; t++) {
        // prefetch xg (hides DRAM latency behind the wait)
        float xgv[4];
        {
            size_t xoff = ((size_t)(b_cell * T_ + t)) * G_;
            #pragma unroll
            for (int g = 0; g < 4; g++)
                xgv[g] = g_xg[xoff + g * 512 + u_cell];
        }

        if (t > 0) {
            // acquire-wait on the single per-bg counter
            if (tid == 0) {
                int target = 32 * t, v;
                do {
                    asm volatile("ld.acquire.gpu.global.s32 %0, [%1];"
                                 : "=r"(v) : "l"(donep));
                } while (v < target);
            }
            __syncthreads();
            const float* src = g_hT2[t & 1];
            #pragma unroll
            for (int chg = 0; chg < 4; chg++) {
                #pragma unroll
                for (int q = 0; q < 2; q++) {
                    int f = tid + q * 256;            // 0..511 16B-chunks
                    int kp = chg * 64 + (f >> 3), j = f & 7;
                    CP_ASYNC16(scr_base + (unsigned)((kp * 36 + j * 4) * 4),
                               (const void*)&src[(size_t)kp * 128 + bg * 32 + j * 4]);
                }
                CP_COMMIT();
            }
        } else {
            #pragma unroll
            for (int i = 0; i < 9; i++)               // zero h2 region
                *(float4*)&scr[(tid + i * 256) * 4] = make_float4(0.f, 0.f, 0.f, 0.f);
        }

        ull acc[8][8] = {};   // [col ci][batch bi], f32x2 over k-parity

        #pragma unroll
        for (int ch = 0; ch < 4; ch++) {
            if (t > 0) {
                switch (ch) {
                    case 0: CP_WAIT(3); break;
                    case 1: CP_WAIT(2); break;
                    case 2: CP_WAIT(1); break;
                    default: CP_WAIT(0); break;
                }
            }
            __syncthreads();
            #pragma unroll
            for (int ii = 0; ii < 4; ii++) {
                int kp = ch * 64 + ii * 16 + kq;
                const ulonglong2* wr = (const ulonglong2*)&W2[kp * 132 + cg * 16];
                ulonglong2 wa = wr[0], wb = wr[1], wc = wr[2], wd = wr[3];
                const ulonglong2* hr = (const ulonglong2*)&scr[kp * 36 + bh * 16];
                ulonglong2 ha = hr[0], hb = hr[1], hc = hr[2], hd = hr[3];
                ull w[8] = {wa.x, wa.y, wb.x, wb.y, wc.x, wc.y, wd.x, wd.y};
                ull h[8] = {ha.x, ha.y, hb.x, hb.y, hc.x, hc.y, hd.x, hd.y};
                #pragma unroll
                for (int ci = 0; ci < 8; ci++)
                    #pragma unroll
                    for (int bi = 0; bi < 8; bi++)
                        FMA2(acc[ci][bi], w[ci], h[bi], acc[ci][bi]);
            }
        }

        // ---- fold k-parity + 16-way kq reduce through scr ----
        __syncthreads();          // all h2 reads done; scr becomes red
        #pragma unroll
        for (int ci = 0; ci < 8; ci++) {
            float s[8];
            #pragma unroll
            for (int bi = 0; bi < 8; bi++) {
                float lo, hi; UNPACK2(lo, hi, acc[ci][bi]);
                s[bi] = lo + hi;
            }
            int base = kq * 1028 + (cg * 8 + ci) * 16 + bh * 8;
            *(float4*)&scr[base]     = make_float4(s[0], s[1], s[2], s[3]);
            *(float4*)&scr[base + 4] = make_float4(s[4], s[5], s[6], s[7]);
        }
        __syncthreads();

        // read-sum: thread -> col rc, batches rbq*4..+4
        {
            float4 vs = make_float4(0.f, 0.f, 0.f, 0.f);
            #pragma unroll
            for (int kqi = 0; kqi < 16; kqi++) {
                float4 v = *(const float4*)&scr[kqi * 1028 + rc * 16 + rbq * 4];
                vs.x += v.x; vs.y += v.y; vs.z += v.z; vs.w += v.w;
            }
            gsum[(rbq * 4 + 0) * 64 + rc] = vs.x;
            gsum[(rbq * 4 + 1) * 64 + rc] = vs.y;
            gsum[(rbq * 4 + 2) * 64 + rc] = vs.z;
            gsum[(rbq * 4 + 3) * 64 + rc] = vs.w;
        }
        __syncthreads();

        // phase 2: one cell per thread, MUFU-based activations
        {
            float s0 = gsum[b_l * 64 + 0 * 16 + u_l] + xgv[0];   // i
            float s1 = gsum[b_l * 64 + 1 * 16 + u_l] + xgv[1];   // j
            float s2 = gsum[b_l * 64 + 2 * 16 + u_l] + xgv[2];   // f
            float s3 = gsum[b_l * 64 + 3 * 16 + u_l] + xgv[3];   // o
            float ig = sigf(s0);
            float jg = tanhfast(s1);
            float fg = sigf(s2 + 1.0f);                           // forget_bias = 1
            float og = sigf(s3);
            creg = fg * creg + ig * jg;
            float h = og * tanhfast(creg);
            hstage[u_l * 16 + b_l] = h;
            g_hs[((size_t)(b_cell * T_ + t)) * H_ + u_cell] = h;
        }
        __syncthreads();
        if (tid < 128) {       // k-pair interleaved mirror write (coalesced ull)
            int kpi = tid >> 4, bi = tid & 15;
            ull hv; PACK2(hv, hstage[(kpi * 2) * 16 + bi], hstage[(kpi * 2 + 1) * 16 + bi]);
            ((ull*)g_hT2[(t + 1) & 1])[(size_t)(ug * 8 + kpi) * 64 + bg * 16 + bi] = hv;
        }
        __threadfence();       // release this thread's h stores (pattern as R6-R8)
        __syncthreads();
        if (tid == 0)
            asm volatile("red.relaxed.gpu.global.add.s32 [%0], %1;"
                         :: "l"(donep), "r"(1) : "memory");
    }
}

// ============================================================
// Kernel C: out_loss (fast sigmoid)
// ============================================================
__global__ void __launch_bounds__(256) out_loss(
    const float* __restrict__ Wd, const float* __restrict__ bd,
    const float* __restrict__ Y)
{
    __shared__ float h_s[512 * 20];
    __shared__ float red[8];
    int tid = threadIdx.x;
    int row0 = blockIdx.x * 16;

    #pragma unroll
    for (int i = 0; i < 32; i++) {
        int idx = tid + i * 256;
        int r = idx >> 9, k = idx & 511;
        h_s[k * 20 + r] = g_hs[(size_t)(row0 + r) * H_ + k];
    }
    __syncthreads();

    int cc = tid & 127;
    int rh = tid >> 7;
    ull acc2[4] = {};
    #pragma unroll 4
    for (int k = 0; k < 512; k++) {
        float w = Wd[(size_t)k * N_ + cc];
        ull wd; PACK2(wd, w, w);
        ulonglong2 ha = *(const ulonglong2*)&h_s[k * 20 + rh * 8];
        ulonglong2 hb = *(const ulonglong2*)&h_s[k * 20 + rh * 8 + 4];
        FMA2(acc2[0], ha.x, wd, acc2[0]);
        FMA2(acc2[1], ha.y, wd, acc2[1]);
        FMA2(acc2[2], hb.x, wd, acc2[2]);
        FMA2(acc2[3], hb.y, wd, acc2[3]);
    }
    float accv[8];
    #pragma unroll
    for (int p = 0; p < 4; p++) UNPACK2(accv[2 * p], accv[2 * p + 1], acc2[p]);

    float bdc = bd[cc];
    float lsum = 0.0f;
    #pragma unroll
    for (int i = 0; i < 8; i++) {
        int row = row0 + rh * 8 + i;
        float logit = sigf(accv[i] + bdc);
        float d = Y[(size_t)row * N_ + cc] - logit;
        lsum += d * d;
    }
    #pragma unroll
    for (int o = 16; o; o >>= 1) lsum += __shfl_xor_sync(0xFFFFFFFFu, lsum, o);
    if ((tid & 31) == 0) red[tid >> 5] = lsum;
    __syncthreads();
    if (tid == 0) {
        float ssum = 0.0f;
        #pragma unroll
        for (int i = 0; i < 8; i++) ssum += red[i];
        g_lpart[blockIdx.x] = ssum;
    }
}

// ============================================================
__global__ void finalize(float* __restrict__ out)
{
    __shared__ float red[8];
    int tid = threadIdx.x;
    float sv = 0.0f;
    for (int i = tid; i < 2048; i += 256) sv += g_lpart[i];
    #pragma unroll
    for (int o = 16; o; o >>= 1) sv += __shfl_xor_sync(0xFFFFFFFFu, sv, o);
    if ((tid & 31) == 0) red[tid >> 5] = sv;
    __syncthreads();
    if (tid == 0) {
        float tt = 0.0f;
        #pragma unroll
        for (int i = 0; i < 8; i++) tt += red[i];
        out[0] = tt * (100.0f / ((float)B_ * (float)T_ * (float)N_));
    }
}

// ============================================================
extern "C" void kernel_launch(void* const* d_in, const int* in_sizes, int n_in,
                              void* d_out, int out_size)
{
    const float* X  = (const float*)d_in[0];
    const float* Y  = (const float*)d_in[1];
    const float* Wx = (const float*)d_in[2];
    const float* Wh = (const float*)d_in[3];
    const float* b  = (const float*)d_in[4];
    const float* Wd = (const float*)d_in[5];
    const float* bd = (const float*)d_in[6];
    (void)in_sizes; (void)n_in; (void)out_size;

    cudaFuncSetAttribute(lstm_scan, cudaFuncAttributeMaxDynamicSharedMemorySize, SMEM_SCAN);

    dim3 gA(G_ / 64, BT_ / 64);
    xg_gemm<<<gA, 256>>>(X, Wx, b);             // also resets g_done
    lstm_scan<<<NBLK, 256, SMEM_SCAN>>>(Wh);
    out_loss<<<BT_ / 16, 256>>>(Wd, bd, Y);
    finalize<<<1, 256>>>((float*)d_out);
}